// round 12
// baseline (speedup 1.0000x reference)
#include <cuda_runtime.h>
#include <cuda_bf16.h>
#include <cuda_fp16.h>
#include <math.h>
#include <stdint.h>

#define BS   2
#define SEQL 2048
#define DM   1024
#define H    16
#define D    64
#define R    (BS*SEQL)   // 4096
#define KE   2048        // expanded K (hi|lo) in fp16 for X
#define NBH  (BS*H)      // 32

// Scratch (__device__ globals — no allocation).
// Q/K/V in split-bf16 packed layout: [bh][seq][128] per 32-d block:
// cols [dblk*64 .. +31] = hi, [dblk*64+32 .. +63] = lo. Row = 256 B.
__device__ __nv_bfloat16 g_Qs[(size_t)NBH*SEQL*128];
__device__ __nv_bfloat16 g_Ks[(size_t)NBH*SEQL*128];
__device__ __nv_bfloat16 g_Vs[(size_t)NBH*SEQL*128];
__device__ __half g_Xp[(size_t)R * KE];               // X hi|lo fp16, 16 MB
__device__ __half g_Wh[(size_t)3 * DM * DM];          // W hi-only fp16, 6 MB

// ===========================================================================
// helpers
// ===========================================================================
__device__ __forceinline__ uint32_t smem_to_u32(const void* p) {
    uint32_t a;
    asm("{ .reg .u64 t; cvta.to.shared.u64 t, %1; cvt.u32.u64 %0, t; }" : "=r"(a) : "l"(p));
    return a;
}
#define SW128(off) ((off) ^ (((off) >> 3) & 0x70))     // 128B rows
#define SWZ256(off) ((off) ^ (((off) >> 4) & 0x70))    // 256B rows

#define CP_ASYNC16(saddr, gptr) \
    asm volatile("cp.async.cg.shared.global [%0], [%1], 16;" :: "r"(saddr), "l"(gptr))
#define CP_COMMIT() asm volatile("cp.async.commit_group;" ::: "memory")
#define CP_WAIT1()  asm volatile("cp.async.wait_group 1;" ::: "memory")
#define CP_WAIT0()  asm volatile("cp.async.wait_group 0;" ::: "memory")

__device__ __forceinline__ void ldmatrix_x4(uint32_t* r, uint32_t addr) {
    asm volatile("ldmatrix.sync.aligned.m8n8.x4.shared.b16 {%0,%1,%2,%3}, [%4];"
        : "=r"(r[0]), "=r"(r[1]), "=r"(r[2]), "=r"(r[3]) : "r"(addr));
}
__device__ __forceinline__ void ldmatrix_x4_trans(uint32_t* r, uint32_t addr) {
    asm volatile("ldmatrix.sync.aligned.m8n8.x4.trans.shared.b16 {%0,%1,%2,%3}, [%4];"
        : "=r"(r[0]), "=r"(r[1]), "=r"(r[2]), "=r"(r[3]) : "r"(addr));
}
__device__ __forceinline__ void mma_bf16(float* d, const uint32_t* a, const uint32_t* b) {
    asm volatile(
        "mma.sync.aligned.m16n8k16.row.col.f32.bf16.bf16.f32 "
        "{%0,%1,%2,%3}, {%4,%5,%6,%7}, {%8,%9}, {%0,%1,%2,%3};"
        : "+f"(d[0]), "+f"(d[1]), "+f"(d[2]), "+f"(d[3])
        : "r"(a[0]), "r"(a[1]), "r"(a[2]), "r"(a[3]), "r"(b[0]), "r"(b[1]));
}
__device__ __forceinline__ void mma_fp16(float* d, const uint32_t* a, const uint32_t* b) {
    asm volatile(
        "mma.sync.aligned.m16n8k16.row.col.f32.f16.f16.f32 "
        "{%0,%1,%2,%3}, {%4,%5,%6,%7}, {%8,%9}, {%0,%1,%2,%3};"
        : "+f"(d[0]), "+f"(d[1]), "+f"(d[2]), "+f"(d[3])
        : "r"(a[0]), "r"(a[1]), "r"(a[2]), "r"(a[3]), "r"(b[0]), "r"(b[1]));
}
__device__ __forceinline__ float ex2(float x) {
    float y; asm("ex2.approx.ftz.f32 %0, %1;" : "=f"(y) : "f"(x)); return y;
}
__device__ __forceinline__ uint32_t packbf2(float a, float b) {
    __nv_bfloat162 t = __floats2bfloat162_rn(a, b);
    return *(uint32_t*)&t;
}
#define LOG2E 1.4426950408889634f

// ===========================================================================
// Fused split kernel.
// X rows -> fp16 hi|lo packed (per 32-k block: [32 hi][32 lo]).
// W rows -> fp16 hi only, plain k-major.
// ===========================================================================
__global__ __launch_bounds__(256) void split_all_kernel(
    const float* __restrict__ X,
    const float* __restrict__ Wq, const float* __restrict__ Wk,
    const float* __restrict__ Wv,
    __half* __restrict__ Xp, __half* __restrict__ Wh)
{
    int blk = blockIdx.x;
    int k = threadIdx.x * 4;
    if (blk < R) {
        const float* src = X + (size_t)blk * DM;
        __half* dstrow = Xp + (size_t)blk * KE;
        float4 v = *(const float4*)(src + k);
        float x[4] = {v.x, v.y, v.z, v.w};
        __half hi[4], lo[4];
        #pragma unroll
        for (int i = 0; i < 4; i++) {
            hi[i] = __float2half_rn(x[i]);
            lo[i] = __float2half_rn(x[i] - __half2float(hi[i]));
        }
        int kblk = k >> 5, kl = k & 31;
        __half* base = dstrow + kblk * 64 + kl;
        *(__half2*)(base + 0)  = __half2{hi[0], hi[1]};
        *(__half2*)(base + 2)  = __half2{hi[2], hi[3]};
        *(__half2*)(base + 32) = __half2{lo[0], lo[1]};
        *(__half2*)(base + 34) = __half2{lo[2], lo[3]};
    } else {
        int w = blk - R;
        int z = w >> 10;
        int row = w & 1023;
        const float* ws = (z == 0) ? Wq : (z == 1) ? Wk : Wv;
        const float* src = ws + (size_t)row * DM;
        __half* dstrow = Wh + ((size_t)z * DM + row) * DM;
        float4 v = *(const float4*)(src + k);
        __half2 h01 = __half2{__float2half_rn(v.x), __float2half_rn(v.y)};
        __half2 h23 = __half2{__float2half_rn(v.z), __float2half_rn(v.w)};
        *(__half2*)(dstrow + k)     = h01;
        *(__half2*)(dstrow + k + 2) = h23;
    }
}

// ===========================================================================
// Projection GEMM via mma.sync fp16, 2-term split: C = (Xhi+Xlo) . Whi^T.
// CTA 128x128, warp tile 64x32 (8 warps: 2M x 4N), BK=64 orig k per stage.
// A stage: 128 rows x 256B (hi|lo, SWZ256). B stage: 128 rows x 128B (SW128).
// 2-stage cp.async (R8/R11-proven schedule). Inner loop restructured for a
// minimal live register set: acc(64) + bf(8) + ahi/alo(8) -> no spills at
// the 128-reg cap from __launch_bounds__(256,2).
// ===========================================================================
#define BM 128
#define BN 128
#define NK (DM/64)                   // 16 iterations
#define STG_A 32768
#define STG_B 16384
#define STG_BYTES (STG_A + STG_B)    // 48KB
#define PROJ_SMEM (2 * STG_BYTES)    // 96KB

__device__ __forceinline__ void proj_load_stage(
    uint32_t sbase, int stage, int kt,
    const char* gA, const char* gB, int tid)
{
    uint32_t sa = sbase + stage * STG_BYTES;
    uint32_t sb = sa + STG_A;
    const char* a = gA + (size_t)kt * 256;
    {
        int row = tid >> 4, c = tid & 15;
        #pragma unroll
        for (int p = 0; p < 8; p++) {
            uint32_t off = SWZ256((uint32_t)((row + p * 16) * 256 + c * 16));
            CP_ASYNC16(sa + off, a + (size_t)(row + p * 16) * 4096 + c * 16);
        }
    }
    const char* b = gB + (size_t)kt * 128;
    {
        int row = tid >> 3, c = tid & 7;
        #pragma unroll
        for (int p = 0; p < 4; p++) {
            uint32_t off = SW128((uint32_t)((row + p * 32) * 128 + c * 16));
            CP_ASYNC16(sb + off, b + (size_t)(row + p * 32) * 2048 + c * 16);
        }
    }
}

__global__ __launch_bounds__(256, 2) void qkv_mma_kernel(
    const float* __restrict__ bq, const float* __restrict__ bk,
    const float* __restrict__ bv)
{
    extern __shared__ char smem[];
    const uint32_t sbase = smem_to_u32(smem);
    const int tid  = threadIdx.x;
    const int wid  = tid >> 5;
    const int lane = tid & 31;
    const int z    = blockIdx.z;

    const float* bias; __nv_bfloat16* Outs; float scale;
    if (z == 0)      { bias = bq; Outs = g_Qs; scale = 0.125f; }
    else if (z == 1) { bias = bk; Outs = g_Ks; scale = 1.0f;   }
    else             { bias = bv; Outs = g_Vs; scale = 1.0f;   }

    const int n0 = blockIdx.x * BN;
    const int m0 = blockIdx.y * BM;

    const char* gA = (const char*)g_Xp + (size_t)m0 * 4096;
    const char* gB = (const char*)(g_Wh + (size_t)z * DM * DM) + (size_t)n0 * 2048;

    // prologue: stage 0 <- kt 0
    proj_load_stage(sbase, 0, 0, gA, gB, tid);
    CP_COMMIT();

    const int wm = (wid & 1) * 64;
    const int wn = (wid >> 1) * 32;
    float acc[4][4][4];
    #pragma unroll
    for (int f = 0; f < 4; f++)
        #pragma unroll
        for (int g = 0; g < 4; g++)
            #pragma unroll
            for (int i = 0; i < 4; i++) acc[f][g][i] = 0.0f;

    const int lrow16 = lane & 15;
    const int lc16   = (lane >> 4) << 4;

    // precomputed per-thread base addresses (loop-invariant)
    const uint32_t arow_base = (uint32_t)((wm + lrow16) * 256) + (uint32_t)lc16;
    const uint32_t brow_base = (uint32_t)((wn + lrow16) * 128) + (uint32_t)lc16;

    for (int kt = 0; kt < NK; kt++) {
        if (kt + 1 < NK) {
            proj_load_stage(sbase, (kt + 1) & 1, kt + 1, gA, gB, tid);
            CP_COMMIT();
            CP_WAIT1();
        } else {
            CP_WAIT0();
        }
        __syncthreads();

        const uint32_t abase = sbase + (kt & 1) * STG_BYTES;
        const uint32_t bbase = abase + STG_A;

        #pragma unroll
        for (int kh = 0; kh < 4; kh++) {      // 4 x k16 per stage (64 k)
            const uint32_t acb = (uint32_t)((kh >> 1) * 128 + (kh & 1) * 32);
            // B fragments for this k16 (8 regs, reused by all f)
            uint32_t bf[4][2];
            #pragma unroll
            for (int g2 = 0; g2 < 2; g2++) {
                uint32_t rr[4];
                ldmatrix_x4(rr, bbase +
                    SW128(brow_base + (uint32_t)(g2 * 16 * 128 + kh * 32)));
                bf[g2 * 2 + 0][0] = rr[0]; bf[g2 * 2 + 0][1] = rr[2];
                bf[g2 * 2 + 1][0] = rr[1]; bf[g2 * 2 + 1][1] = rr[3];
            }
            // per m-fragment: load A hi/lo (8 regs), 8 MMAs, release
            #pragma unroll
            for (int f = 0; f < 4; f++) {
                uint32_t ahi[4], alo[4];
                uint32_t arow = arow_base + (uint32_t)(f * 16 * 256) + acb;
                ldmatrix_x4(ahi, abase + SWZ256(arow));
                ldmatrix_x4(alo, abase + SWZ256(arow + 64));
                #pragma unroll
                for (int g = 0; g < 4; g++) {
                    mma_fp16(acc[f][g], ahi, bf[g]);   // xhi * whi
                    mma_fp16(acc[f][g], alo, bf[g]);   // xlo * whi
                }
            }
        }
        __syncthreads();   // protect stage kt&1 from next iteration's prefetch
    }

    // Epilogue: bias + scale, hi/lo bf16 split, scatter into [bh][s][128].
    const int gq = lane >> 2;
    const int gt = lane & 3;
    #pragma unroll
    for (int f = 0; f < 4; f++) {
        #pragma unroll
        for (int g = 0; g < 4; g++) {
            int col = n0 + wn + g * 8 + 2 * gt;
            int h_  = col >> 6;
            int dd  = col & 63;
            int dblk = dd >> 5, pos = dd & 31;
            float b0 = __ldg(&bias[col]), b1 = __ldg(&bias[col + 1]);
            #pragma unroll
            for (int half = 0; half < 2; half++) {
                int m_abs = m0 + wm + f * 16 + gq + half * 8;
                int bb = m_abs >> 11;
                int ss = m_abs & (SEQL - 1);
                float vx = (acc[f][g][half * 2 + 0] + b0) * scale;
                float vy = (acc[f][g][half * 2 + 1] + b1) * scale;
                __nv_bfloat16 hx = __float2bfloat16(vx);
                __nv_bfloat16 hy = __float2bfloat16(vy);
                __nv_bfloat16 lx = __float2bfloat16(vx - __bfloat162float(hx));
                __nv_bfloat16 ly = __float2bfloat16(vy - __bfloat162float(hy));
                size_t base = ((size_t)((bb * H + h_) * SEQL + ss)) * 128 + dblk * 64 + pos;
                *(__nv_bfloat162*)(Outs + base)      = __nv_bfloat162{hx, hy};
                *(__nv_bfloat162*)(Outs + base + 32) = __nv_bfloat162{lx, ly};
            }
        }
    }
}

// ===========================================================================
// Attention via mma.sync bf16 split (3 cross terms), flash online softmax.
// (unchanged — proven at ~225us)
// ===========================================================================
#define AKT 32
#define ANIT (SEQL/AKT)      // 64
#define SQ_OFF 0
#define SK_OFF 32768
#define SV_OFF 49152
#define SB_OFF 65536
#define ATT_SMEM 73728

__global__ __launch_bounds__(256, 1) void attn_mma_kernel(
    const int* __restrict__ mask, float* __restrict__ out)
{
    extern __shared__ char smem[];
    const uint32_t sbase = smem_to_u32(smem);
    const uint32_t sQ = sbase + SQ_OFF;
    const uint32_t sK = sbase + SK_OFF;
    const uint32_t sV = sbase + SV_OFF;
    float* sbias = (float*)(smem + SB_OFF);

    const int tid  = threadIdx.x;
    const int wid  = tid >> 5;
    const int lane = tid & 31;
    const int gq   = lane >> 2;
    const int gt   = lane & 3;
    const int bh   = blockIdx.y;
    const int b    = bh >> 4;
    const int h_   = bh & 15;
    const int qr0  = blockIdx.x * 128;
    const int qw   = wid * 16;

    const char* Qg = (const char*)(g_Qs + ((size_t)bh * SEQL + qr0) * 128);
    const char* Kg = (const char*)(g_Ks + (size_t)bh * SEQL * 128);
    const char* Vg = (const char*)(g_Vs + (size_t)bh * SEQL * 128);

    {
        #pragma unroll
        for (int i = 0; i < 8; i++) {
            int idx = tid + i * 256;
            int row = idx >> 4, c = idx & 15;
            CP_ASYNC16(sQ + SWZ256((uint32_t)(row * 256 + c * 16)),
                       Qg + (size_t)row * 256 + c * 16);
        }
        #pragma unroll
        for (int i = 0; i < 2; i++) {
            int idx = tid + i * 256;
            int row = idx >> 4, c = idx & 15;
            uint32_t off = SWZ256((uint32_t)(row * 256 + c * 16));
            CP_ASYNC16(sK + off, Kg + (size_t)row * 256 + c * 16);
            CP_ASYNC16(sV + off, Vg + (size_t)row * 256 + c * 16);
        }
        CP_COMMIT();
        #pragma unroll
        for (int i = 0; i < 8; i++) {
            int j = tid + i * 256;
            sbias[j] = mask[b * SEQL + j] ? 0.0f : -2.6e29f;
        }
    }

    uint32_t qf[2][4][4];
    float oacc[8][4];
    #pragma unroll
    for (int j = 0; j < 8; j++)
        #pragma unroll
        for (int i = 0; i < 4; i++) oacc[j][i] = 0.0f;
    float m0 = -INFINITY, m1 = -INFINITY, l0 = 0.0f, l1 = 0.0f;

    for (int kt = 0; kt < ANIT; kt++) {
        if (kt + 1 < ANIT) {
            uint32_t dstK = sK + ((kt + 1) & 1) * 8192;
            uint32_t dstV = sV + ((kt + 1) & 1) * 8192;
            const char* kg = Kg + (size_t)(kt + 1) * AKT * 256;
            const char* vg = Vg + (size_t)(kt + 1) * AKT * 256;
            #pragma unroll
            for (int i = 0; i < 2; i++) {
                int idx = tid + i * 256;
                int row = idx >> 4, c = idx & 15;
                uint32_t off = SWZ256((uint32_t)(row * 256 + c * 16));
                CP_ASYNC16(dstK + off, kg + (size_t)row * 256 + c * 16);
                CP_ASYNC16(dstV + off, vg + (size_t)row * 256 + c * 16);
            }
            CP_COMMIT();
            CP_WAIT1();
        } else {
            CP_WAIT0();
        }
        __syncthreads();

        if (kt == 0) {
            #pragma unroll
            for (int hl = 0; hl < 2; hl++)
                #pragma unroll
                for (int s = 0; s < 4; s++) {
                    int row = qw + (lane & 15);
                    int cb  = (s >> 1) * 128 + hl * 64 + (s & 1) * 32 + ((lane >> 4) << 4);
                    ldmatrix_x4(qf[hl][s], sQ + SWZ256((uint32_t)(row * 256 + cb)));
                }
        }

        const uint32_t Kst = sK + (kt & 1) * 8192;
        const uint32_t Vst = sV + (kt & 1) * 8192;

        float sacc[4][4];
        #pragma unroll
        for (int j = 0; j < 4; j++)
            #pragma unroll
            for (int i = 0; i < 4; i++) sacc[j][i] = 0.0f;

        #pragma unroll
        for (int s = 0; s < 4; s++) {
            int rowb = (lane & 15);
            int cbase = (s >> 1) * 128 + (s & 1) * 32 + ((lane >> 4) << 4);
            uint32_t bhi[4][2], blo[4][2];
            #pragma unroll
            for (int g2 = 0; g2 < 2; g2++) {
                uint32_t rr[4];
                ldmatrix_x4(rr, Kst + SWZ256((uint32_t)((g2 * 16 + rowb) * 256 + cbase)));
                bhi[g2 * 2 + 0][0] = rr[0]; bhi[g2 * 2 + 0][1] = rr[2];
                bhi[g2 * 2 + 1][0] = rr[1]; bhi[g2 * 2 + 1][1] = rr[3];
            }
            #pragma unroll
            for (int j = 0; j < 4; j++) {
                mma_bf16(sacc[j], qf[0][s], bhi[j]);
                mma_bf16(sacc[j], qf[1][s], bhi[j]);
            }
            #pragma unroll
            for (int g2 = 0; g2 < 2; g2++) {
                uint32_t rr[4];
                ldmatrix_x4(rr, Kst + SWZ256((uint32_t)((g2 * 16 + rowb) * 256 + cbase + 64)));
                blo[g2 * 2 + 0][0] = rr[0]; blo[g2 * 2 + 0][1] = rr[2];
                blo[g2 * 2 + 1][0] = rr[1]; blo[g2 * 2 + 1][1] = rr[3];
            }
            #pragma unroll
            for (int j = 0; j < 4; j++)
                mma_bf16(sacc[j], qf[0][s], blo[j]);
        }

        float mx0 = -INFINITY, mx1 = -INFINITY;
        #pragma unroll
        for (int j = 0; j < 4; j++) {
            float2 bb = *(float2*)&sbias[kt * AKT + j * 8 + 2 * gt];
            sacc[j][0] = fmaf(sacc[j][0], LOG2E, bb.x);
            sacc[j][1] = fmaf(sacc[j][1], LOG2E, bb.y);
            sacc[j][2] = fmaf(sacc[j][2], LOG2E, bb.x);
            sacc[j][3] = fmaf(sacc[j][3], LOG2E, bb.y);
            mx0 = fmaxf(mx0, fmaxf(sacc[j][0], sacc[j][1]));
            mx1 = fmaxf(mx1, fmaxf(sacc[j][2], sacc[j][3]));
        }
        mx0 = fmaxf(mx0, __shfl_xor_sync(0xFFFFFFFF, mx0, 1));
        mx0 = fmaxf(mx0, __shfl_xor_sync(0xFFFFFFFF, mx0, 2));
        mx1 = fmaxf(mx1, __shfl_xor_sync(0xFFFFFFFF, mx1, 1));
        mx1 = fmaxf(mx1, __shfl_xor_sync(0xFFFFFFFF, mx1, 2));
        float mn0 = fmaxf(m0, mx0), mn1 = fmaxf(m1, mx1);
        float c0 = ex2(m0 - mn0), c1 = ex2(m1 - mn1);
        m0 = mn0; m1 = mn1;
        l0 *= c0;  l1 *= c1;
        #pragma unroll
        for (int j = 0; j < 8; j++) {
            oacc[j][0] *= c0; oacc[j][1] *= c0;
            oacc[j][2] *= c1; oacc[j][3] *= c1;
        }

        uint32_t phiA[2][4], ploA[2][4];
        float ls0 = 0.0f, ls1 = 0.0f;
        #pragma unroll
        for (int j = 0; j < 4; j++) {
            float p0 = ex2(sacc[j][0] - mn0);
            float p1 = ex2(sacc[j][1] - mn0);
            float p2 = ex2(sacc[j][2] - mn1);
            float p3 = ex2(sacc[j][3] - mn1);
            ls0 += p0 + p1; ls1 += p2 + p3;
            __nv_bfloat16 h0 = __float2bfloat16(p0), h1 = __float2bfloat16(p1);
            __nv_bfloat16 h2 = __float2bfloat16(p2), h3 = __float2bfloat16(p3);
            int t = j >> 1, hf = (j & 1) * 2;
            phiA[t][hf + 0] = packbf2(__bfloat162float(h0), __bfloat162float(h1));
            phiA[t][hf + 1] = packbf2(__bfloat162float(h2), __bfloat162float(h3));
            ploA[t][hf + 0] = packbf2(p0 - __bfloat162float(h0), p1 - __bfloat162float(h1));
            ploA[t][hf + 1] = packbf2(p2 - __bfloat162float(h2), p3 - __bfloat162float(h3));
        }
        l0 += ls0; l1 += ls1;

        #pragma unroll
        for (int t = 0; t < 2; t++) {
            int rowb = t * 16 + (lane & 15);
            uint32_t vhi[8][2], vlo[8][2];
            #pragma unroll
            for (int nc = 0; nc < 4; nc++) {
                int cb = (nc >> 1) * 128 + (nc & 1) * 32 + ((lane >> 4) << 4);
                uint32_t rr[4];
                ldmatrix_x4_trans(rr, Vst + SWZ256((uint32_t)(rowb * 256 + cb)));
                vhi[nc * 2 + 0][0] = rr[0]; vhi[nc * 2 + 0][1] = rr[1];
                vhi[nc * 2 + 1][0] = rr[2]; vhi[nc * 2 + 1][1] = rr[3];
            }
            #pragma unroll
            for (int jn = 0; jn < 8; jn++) {
                mma_bf16(oacc[jn], phiA[t], vhi[jn]);
                mma_bf16(oacc[jn], ploA[t], vhi[jn]);
            }
            #pragma unroll
            for (int nc = 0; nc < 4; nc++) {
                int cb = (nc >> 1) * 128 + 64 + (nc & 1) * 32 + ((lane >> 4) << 4);
                uint32_t rr[4];
                ldmatrix_x4_trans(rr, Vst + SWZ256((uint32_t)(rowb * 256 + cb)));
                vlo[nc * 2 + 0][0] = rr[0]; vlo[nc * 2 + 0][1] = rr[1];
                vlo[nc * 2 + 1][0] = rr[2]; vlo[nc * 2 + 1][1] = rr[3];
            }
            #pragma unroll
            for (int jn = 0; jn < 8; jn++)
                mma_bf16(oacc[jn], phiA[t], vlo[jn]);
        }
        __syncthreads();
    }

    l0 += __shfl_xor_sync(0xFFFFFFFF, l0, 1);
    l0 += __shfl_xor_sync(0xFFFFFFFF, l0, 2);
    l1 += __shfl_xor_sync(0xFFFFFFFF, l1, 1);
    l1 += __shfl_xor_sync(0xFFFFFFFF, l1, 2);
    float inv0 = 1.0f / l0, inv1 = 1.0f / l1;

    int r0 = qr0 + qw + gq;
    int r1 = r0 + 8;
    float* o0 = out + ((size_t)b * SEQL + r0) * DM + h_ * D;
    float* o1 = out + ((size_t)b * SEQL + r1) * DM + h_ * D;
    #pragma unroll
    for (int jn = 0; jn < 8; jn++) {
        int dc = jn * 8 + 2 * gt;
        *(float2*)(o0 + dc) = float2{oacc[jn][0] * inv0, oacc[jn][1] * inv0};
        *(float2*)(o1 + dc) = float2{oacc[jn][2] * inv1, oacc[jn][3] * inv1};
    }
}

// ---------------------------------------------------------------------------
extern "C" void kernel_launch(void* const* d_in, const int* in_sizes, int n_in,
                              void* d_out, int out_size)
{
    const float* X    = (const float*)d_in[0];
    const int*   mask = (const int*)  d_in[1];
    const float* Wq   = (const float*)d_in[2];
    const float* bq   = (const float*)d_in[3];
    const float* Wk   = (const float*)d_in[4];
    const float* bk   = (const float*)d_in[5];
    const float* Wv   = (const float*)d_in[6];
    const float* bv   = (const float*)d_in[7];

    __half* xp; cudaGetSymbolAddress((void**)&xp, g_Xp);
    __half* wh; cudaGetSymbolAddress((void**)&wh, g_Wh);

    // 1) fused split: X -> fp16 hi|lo, W -> fp16 hi
    split_all_kernel<<<R + 3 * DM, 256>>>(X, Wq, Wk, Wv, xp, wh);

    // 2) QKV projection on tensor cores (fp16 2-term) -> split-bf16 Q/K/V
    cudaFuncSetAttribute(qkv_mma_kernel,
                         cudaFuncAttributeMaxDynamicSharedMemorySize, PROJ_SMEM);
    dim3 g1(DM / BN, R / BM, 3);                           // (8, 32, 3)
    qkv_mma_kernel<<<g1, 256, PROJ_SMEM>>>(bq, bk, bv);

    // 3) attention on tensor cores (bf16 3-term, unchanged)
    cudaFuncSetAttribute(attn_mma_kernel,
                         cudaFuncAttributeMaxDynamicSharedMemorySize, ATT_SMEM);
    dim3 g2(SEQL / 128, NBH);
    attn_mma_kernel<<<g2, 256, ATT_SMEM>>>(mask, (float*)d_out);
}

// round 15
// speedup vs baseline: 1.2719x; 1.2719x over previous
#include <cuda_runtime.h>
#include <cuda_bf16.h>
#include <cuda_fp16.h>
#include <math.h>
#include <stdint.h>

#define BS   2
#define SEQL 2048
#define DM   1024
#define H    16
#define D    64
#define R    (BS*SEQL)   // 4096
#define KE   2048        // expanded K (hi|lo) in fp16 for X
#define NBH  (BS*H)      // 32

// Scratch (__device__ globals — no allocation).
// Q: fp16 hi|lo packed [bh][seq][128]: per 32-d block [32 hi][32 lo], row 256B.
// K/V: fp16 hi-only [bh][seq][64], row 128B.
__device__ __half g_Qs[(size_t)NBH*SEQL*128];
__device__ __half g_Ks[(size_t)NBH*SEQL*64];
__device__ __half g_Vs[(size_t)NBH*SEQL*64];
__device__ __half g_Xp[(size_t)R * KE];               // X hi|lo fp16, 16 MB
__device__ __half g_Wh[(size_t)3 * DM * DM];          // W hi-only fp16, 6 MB

// ===========================================================================
// helpers
// ===========================================================================
__device__ __forceinline__ uint32_t smem_to_u32(const void* p) {
    uint32_t a;
    asm("{ .reg .u64 t; cvta.to.shared.u64 t, %1; cvt.u32.u64 %0, t; }" : "=r"(a) : "l"(p));
    return a;
}
#define SW128(off) ((off) ^ (((off) >> 3) & 0x70))     // 128B rows
#define SWZ256(off) ((off) ^ (((off) >> 4) & 0x70))    // 256B rows

#define CP_ASYNC16(saddr, gptr) \
    asm volatile("cp.async.cg.shared.global [%0], [%1], 16;" :: "r"(saddr), "l"(gptr))
#define CP_COMMIT() asm volatile("cp.async.commit_group;" ::: "memory")
#define CP_WAIT1()  asm volatile("cp.async.wait_group 1;" ::: "memory")
#define CP_WAIT0()  asm volatile("cp.async.wait_group 0;" ::: "memory")

__device__ __forceinline__ void ldmatrix_x4(uint32_t* r, uint32_t addr) {
    asm volatile("ldmatrix.sync.aligned.m8n8.x4.shared.b16 {%0,%1,%2,%3}, [%4];"
        : "=r"(r[0]), "=r"(r[1]), "=r"(r[2]), "=r"(r[3]) : "r"(addr));
}
__device__ __forceinline__ void ldmatrix_x4_trans(uint32_t* r, uint32_t addr) {
    asm volatile("ldmatrix.sync.aligned.m8n8.x4.trans.shared.b16 {%0,%1,%2,%3}, [%4];"
        : "=r"(r[0]), "=r"(r[1]), "=r"(r[2]), "=r"(r[3]) : "r"(addr));
}
__device__ __forceinline__ void mma_fp16(float* d, const uint32_t* a, const uint32_t* b) {
    asm volatile(
        "mma.sync.aligned.m16n8k16.row.col.f32.f16.f16.f32 "
        "{%0,%1,%2,%3}, {%4,%5,%6,%7}, {%8,%9}, {%0,%1,%2,%3};"
        : "+f"(d[0]), "+f"(d[1]), "+f"(d[2]), "+f"(d[3])
        : "r"(a[0]), "r"(a[1]), "r"(a[2]), "r"(a[3]), "r"(b[0]), "r"(b[1]));
}
__device__ __forceinline__ float ex2(float x) {
    float y; asm("ex2.approx.ftz.f32 %0, %1;" : "=f"(y) : "f"(x)); return y;
}
__device__ __forceinline__ uint32_t packh2(float a, float b) {
    __half2 t = __floats2half2_rn(a, b);
    return *(uint32_t*)&t;
}
#define LOG2E 1.4426950408889634f

// ===========================================================================
// Fused split kernel.
// X rows -> fp16 hi|lo packed (per 32-k block: [32 hi][32 lo]).
// W rows -> fp16 hi only, plain k-major.
// ===========================================================================
__global__ __launch_bounds__(256) void split_all_kernel(
    const float* __restrict__ X,
    const float* __restrict__ Wq, const float* __restrict__ Wk,
    const float* __restrict__ Wv,
    __half* __restrict__ Xp, __half* __restrict__ Wh)
{
    int blk = blockIdx.x;
    int k = threadIdx.x * 4;
    if (blk < R) {
        const float* src = X + (size_t)blk * DM;
        __half* dstrow = Xp + (size_t)blk * KE;
        float4 v = *(const float4*)(src + k);
        float x[4] = {v.x, v.y, v.z, v.w};
        __half hi[4], lo[4];
        #pragma unroll
        for (int i = 0; i < 4; i++) {
            hi[i] = __float2half_rn(x[i]);
            lo[i] = __float2half_rn(x[i] - __half2float(hi[i]));
        }
        int kblk = k >> 5, kl = k & 31;
        __half* base = dstrow + kblk * 64 + kl;
        *(__half2*)(base + 0)  = __half2{hi[0], hi[1]};
        *(__half2*)(base + 2)  = __half2{hi[2], hi[3]};
        *(__half2*)(base + 32) = __half2{lo[0], lo[1]};
        *(__half2*)(base + 34) = __half2{lo[2], lo[3]};
    } else {
        int w = blk - R;
        int z = w >> 10;
        int row = w & 1023;
        const float* ws = (z == 0) ? Wq : (z == 1) ? Wk : Wv;
        const float* src = ws + (size_t)row * DM;
        __half* dstrow = Wh + ((size_t)z * DM + row) * DM;
        float4 v = *(const float4*)(src + k);
        *(__half2*)(dstrow + k)     = __half2{__float2half_rn(v.x), __float2half_rn(v.y)};
        *(__half2*)(dstrow + k + 2) = __half2{__float2half_rn(v.z), __float2half_rn(v.w)};
    }
}

// ===========================================================================
// Projection GEMM via mma.sync fp16, 2-term split: C = (Xhi+Xlo) . Whi^T.
// (R11-proven kernel; only the epilogue output format changed:
//  Q -> fp16 hi|lo [bh][s][128], K/V -> fp16 hi-only [bh][s][64].)
// ===========================================================================
#define BM 128
#define BN 128
#define NK (DM/64)                   // 16 iterations
#define STG_A 32768
#define STG_B 16384
#define STG_BYTES (STG_A + STG_B)    // 48KB
#define PROJ_SMEM (2 * STG_BYTES)    // 96KB

__device__ __forceinline__ void proj_load_stage(
    uint32_t sbase, int stage, int kt,
    const char* gA, const char* gB, int tid)
{
    uint32_t sa = sbase + stage * STG_BYTES;
    uint32_t sb = sa + STG_A;
    const char* a = gA + (size_t)kt * 256;
    {
        int row = tid >> 4, c = tid & 15;
        #pragma unroll
        for (int p = 0; p < 8; p++) {
            uint32_t off = SWZ256((uint32_t)((row + p * 16) * 256 + c * 16));
            CP_ASYNC16(sa + off, a + (size_t)(row + p * 16) * 4096 + c * 16);
        }
    }
    const char* b = gB + (size_t)kt * 128;
    {
        int row = tid >> 3, c = tid & 7;
        #pragma unroll
        for (int p = 0; p < 4; p++) {
            uint32_t off = SW128((uint32_t)((row + p * 32) * 128 + c * 16));
            CP_ASYNC16(sb + off, b + (size_t)(row + p * 32) * 2048 + c * 16);
        }
    }
}

__global__ __launch_bounds__(256, 2) void qkv_mma_kernel(
    const float* __restrict__ bq, const float* __restrict__ bk,
    const float* __restrict__ bv)
{
    extern __shared__ char smem[];
    const uint32_t sbase = smem_to_u32(smem);
    const int tid  = threadIdx.x;
    const int wid  = tid >> 5;
    const int lane = tid & 31;
    const int z    = blockIdx.z;

    const float* bias; __half* Outs; float scale;
    if (z == 0)      { bias = bq; Outs = g_Qs; scale = 0.125f; }
    else if (z == 1) { bias = bk; Outs = g_Ks; scale = 1.0f;   }
    else             { bias = bv; Outs = g_Vs; scale = 1.0f;   }

    const int n0 = blockIdx.x * BN;
    const int m0 = blockIdx.y * BM;

    const char* gA = (const char*)g_Xp + (size_t)m0 * 4096;
    const char* gB = (const char*)(g_Wh + (size_t)z * DM * DM) + (size_t)n0 * 2048;

    proj_load_stage(sbase, 0, 0, gA, gB, tid);
    CP_COMMIT();

    const int wm = (wid & 1) * 64;
    const int wn = (wid >> 1) * 32;
    float acc[4][4][4];
    #pragma unroll
    for (int f = 0; f < 4; f++)
        #pragma unroll
        for (int g = 0; g < 4; g++)
            #pragma unroll
            for (int i = 0; i < 4; i++) acc[f][g][i] = 0.0f;

    const int lrow16 = lane & 15;
    const int lc16   = (lane >> 4) << 4;
    const uint32_t arow_base = (uint32_t)((wm + lrow16) * 256) + (uint32_t)lc16;
    const uint32_t brow_base = (uint32_t)((wn + lrow16) * 128) + (uint32_t)lc16;

    for (int kt = 0; kt < NK; kt++) {
        if (kt + 1 < NK) {
            proj_load_stage(sbase, (kt + 1) & 1, kt + 1, gA, gB, tid);
            CP_COMMIT();
            CP_WAIT1();
        } else {
            CP_WAIT0();
        }
        __syncthreads();

        const uint32_t abase = sbase + (kt & 1) * STG_BYTES;
        const uint32_t bbase = abase + STG_A;

        #pragma unroll
        for (int kh = 0; kh < 4; kh++) {
            const uint32_t acb = (uint32_t)((kh >> 1) * 128 + (kh & 1) * 32);
            uint32_t bf[4][2];
            #pragma unroll
            for (int g2 = 0; g2 < 2; g2++) {
                uint32_t rr[4];
                ldmatrix_x4(rr, bbase +
                    SW128(brow_base + (uint32_t)(g2 * 16 * 128 + kh * 32)));
                bf[g2 * 2 + 0][0] = rr[0]; bf[g2 * 2 + 0][1] = rr[2];
                bf[g2 * 2 + 1][0] = rr[1]; bf[g2 * 2 + 1][1] = rr[3];
            }
            #pragma unroll
            for (int f = 0; f < 4; f++) {
                uint32_t ahi[4], alo[4];
                uint32_t arow = arow_base + (uint32_t)(f * 16 * 256) + acb;
                ldmatrix_x4(ahi, abase + SWZ256(arow));
                ldmatrix_x4(alo, abase + SWZ256(arow + 64));
                #pragma unroll
                for (int g = 0; g < 4; g++) {
                    mma_fp16(acc[f][g], ahi, bf[g]);   // xhi * whi
                    mma_fp16(acc[f][g], alo, bf[g]);   // xlo * whi
                }
            }
        }
        __syncthreads();
    }

    // Epilogue: bias + scale; Q -> fp16 hi|lo, K/V -> fp16 hi-only.
    const int gq = lane >> 2;
    const int gt = lane & 3;
    #pragma unroll
    for (int f = 0; f < 4; f++) {
        #pragma unroll
        for (int g = 0; g < 4; g++) {
            int col = n0 + wn + g * 8 + 2 * gt;
            int h_  = col >> 6;
            int dd  = col & 63;
            float b0 = __ldg(&bias[col]), b1 = __ldg(&bias[col + 1]);
            #pragma unroll
            for (int half = 0; half < 2; half++) {
                int m_abs = m0 + wm + f * 16 + gq + half * 8;
                int bb = m_abs >> 11;
                int ss = m_abs & (SEQL - 1);
                float vx = (acc[f][g][half * 2 + 0] + b0) * scale;
                float vy = (acc[f][g][half * 2 + 1] + b1) * scale;
                __half hx = __float2half_rn(vx);
                __half hy = __float2half_rn(vy);
                if (z == 0) {
                    int dblk = dd >> 5, pos = dd & 31;
                    __half lx = __float2half_rn(vx - __half2float(hx));
                    __half ly = __float2half_rn(vy - __half2float(hy));
                    size_t base = ((size_t)((bb * H + h_) * SEQL + ss)) * 128 + dblk * 64 + pos;
                    *(__half2*)(Outs + base)      = __half2{hx, hy};
                    *(__half2*)(Outs + base + 32) = __half2{lx, ly};
                } else {
                    size_t base = ((size_t)((bb * H + h_) * SEQL + ss)) * 64 + dd;
                    *(__half2*)(Outs + base) = __half2{hx, hy};
                }
            }
        }
    }
}

// ===========================================================================
// Attention via mma.sync fp16 2-term: S = (Qhi+Qlo).Khi^T, O = (Phi+Plo).Vhi.
// CTA: 256 thr (8 warps), 128 q-rows of one bh; KT=32 keys/iter, 64 iters.
// SMEM: Q 32KB | K 2x4KB | V 2x4KB | bias 8KB = 56KB.
// ===========================================================================
#define AKT 32
#define ANIT (SEQL/AKT)      // 64
#define SQ_OFF 0
#define SK_OFF 32768
#define SV_OFF 40960
#define SB_OFF 49152
#define ATT_SMEM 57344

__global__ __launch_bounds__(256, 1) void attn_mma_kernel(
    const int* __restrict__ mask, float* __restrict__ out)
{
    extern __shared__ char smem[];
    const uint32_t sbase = smem_to_u32(smem);
    const uint32_t sQ = sbase + SQ_OFF;
    const uint32_t sK = sbase + SK_OFF;
    const uint32_t sV = sbase + SV_OFF;
    float* sbias = (float*)(smem + SB_OFF);

    const int tid  = threadIdx.x;
    const int wid  = tid >> 5;
    const int lane = tid & 31;
    const int gq   = lane >> 2;
    const int gt   = lane & 3;
    const int bh   = blockIdx.y;
    const int b    = bh >> 4;
    const int h_   = bh & 15;
    const int qr0  = blockIdx.x * 128;
    const int qw   = wid * 16;

    const char* Qg = (const char*)(g_Qs + ((size_t)bh * SEQL + qr0) * 128);
    const char* Kg = (const char*)(g_Ks + (size_t)bh * SEQL * 64);
    const char* Vg = (const char*)(g_Vs + (size_t)bh * SEQL * 64);

    {
        // Q: 32KB = 8 x 16B per thread
        #pragma unroll
        for (int i = 0; i < 8; i++) {
            int idx = tid + i * 256;
            int row = idx >> 4, c = idx & 15;
            CP_ASYNC16(sQ + SWZ256((uint32_t)(row * 256 + c * 16)),
                       Qg + (size_t)row * 256 + c * 16);
        }
        // K0,V0: 4KB each = 1 x 16B per thread
        {
            int row = tid >> 3, c = tid & 7;
            uint32_t off = SW128((uint32_t)(row * 128 + c * 16));
            CP_ASYNC16(sK + off, Kg + (size_t)row * 128 + c * 16);
            CP_ASYNC16(sV + off, Vg + (size_t)row * 128 + c * 16);
        }
        CP_COMMIT();
        #pragma unroll
        for (int i = 0; i < 8; i++) {
            int j = tid + i * 256;
            sbias[j] = mask[b * SEQL + j] ? 0.0f : -2.6e29f;
        }
    }

    uint32_t qf[2][4][4];     // [hi/lo][k16 chunk][regs]
    float oacc[8][4];
    #pragma unroll
    for (int j = 0; j < 8; j++)
        #pragma unroll
        for (int i = 0; i < 4; i++) oacc[j][i] = 0.0f;
    float m0 = -INFINITY, m1 = -INFINITY, l0 = 0.0f, l1 = 0.0f;

    const int rowb = lane & 15;
    const int lc16 = (lane >> 4) << 4;

    for (int kt = 0; kt < ANIT; kt++) {
        if (kt + 1 < ANIT) {
            uint32_t dstK = sK + ((kt + 1) & 1) * 4096;
            uint32_t dstV = sV + ((kt + 1) & 1) * 4096;
            const char* kg = Kg + (size_t)(kt + 1) * AKT * 128;
            const char* vg = Vg + (size_t)(kt + 1) * AKT * 128;
            {
                int row = tid >> 3, c = tid & 7;
                uint32_t off = SW128((uint32_t)(row * 128 + c * 16));
                CP_ASYNC16(dstK + off, kg + (size_t)row * 128 + c * 16);
                CP_ASYNC16(dstV + off, vg + (size_t)row * 128 + c * 16);
            }
            CP_COMMIT();
            CP_WAIT1();
        } else {
            CP_WAIT0();
        }
        __syncthreads();

        if (kt == 0) {   // Q fragments once
            #pragma unroll
            for (int hl = 0; hl < 2; hl++)
                #pragma unroll
                for (int s = 0; s < 4; s++) {
                    int row = qw + rowb;
                    int cb  = (s >> 1) * 128 + hl * 64 + (s & 1) * 32 + lc16;
                    ldmatrix_x4(qf[hl][s], sQ + SWZ256((uint32_t)(row * 256 + cb)));
                }
        }

        const uint32_t Kst = sK + (kt & 1) * 4096;
        const uint32_t Vst = sV + (kt & 1) * 4096;

        // ---- S = (Qhi+Qlo) . Khi^T ----
        float sacc[4][4];
        #pragma unroll
        for (int j = 0; j < 4; j++)
            #pragma unroll
            for (int i = 0; i < 4; i++) sacc[j][i] = 0.0f;

        #pragma unroll
        for (int s = 0; s < 4; s++) {
            uint32_t khi[4][2];
            #pragma unroll
            for (int g2 = 0; g2 < 2; g2++) {
                uint32_t rr[4];
                ldmatrix_x4(rr, Kst +
                    SW128((uint32_t)((g2 * 16 + rowb) * 128 + s * 32 + lc16)));
                khi[g2 * 2 + 0][0] = rr[0]; khi[g2 * 2 + 0][1] = rr[2];
                khi[g2 * 2 + 1][0] = rr[1]; khi[g2 * 2 + 1][1] = rr[3];
            }
            #pragma unroll
            for (int j = 0; j < 4; j++) {
                mma_fp16(sacc[j], qf[0][s], khi[j]);   // qhi * khi
                mma_fp16(sacc[j], qf[1][s], khi[j]);   // qlo * khi
            }
        }

        // ---- mask bias + online softmax (log2 domain) ----
        float mx0 = -INFINITY, mx1 = -INFINITY;
        #pragma unroll
        for (int j = 0; j < 4; j++) {
            float2 bb = *(float2*)&sbias[kt * AKT + j * 8 + 2 * gt];
            sacc[j][0] = fmaf(sacc[j][0], LOG2E, bb.x);
            sacc[j][1] = fmaf(sacc[j][1], LOG2E, bb.y);
            sacc[j][2] = fmaf(sacc[j][2], LOG2E, bb.x);
            sacc[j][3] = fmaf(sacc[j][3], LOG2E, bb.y);
            mx0 = fmaxf(mx0, fmaxf(sacc[j][0], sacc[j][1]));
            mx1 = fmaxf(mx1, fmaxf(sacc[j][2], sacc[j][3]));
        }
        mx0 = fmaxf(mx0, __shfl_xor_sync(0xFFFFFFFF, mx0, 1));
        mx0 = fmaxf(mx0, __shfl_xor_sync(0xFFFFFFFF, mx0, 2));
        mx1 = fmaxf(mx1, __shfl_xor_sync(0xFFFFFFFF, mx1, 1));
        mx1 = fmaxf(mx1, __shfl_xor_sync(0xFFFFFFFF, mx1, 2));
        float mn0 = fmaxf(m0, mx0), mn1 = fmaxf(m1, mx1);
        float c0 = ex2(m0 - mn0), c1 = ex2(m1 - mn1);
        m0 = mn0; m1 = mn1;
        l0 *= c0;  l1 *= c1;
        #pragma unroll
        for (int j = 0; j < 8; j++) {
            oacc[j][0] *= c0; oacc[j][1] *= c0;
            oacc[j][2] *= c1; oacc[j][3] *= c1;
        }

        // ---- P = ex2(S - m), split fp16 hi/lo ----
        uint32_t phiA[2][4], ploA[2][4];
        float ls0 = 0.0f, ls1 = 0.0f;
        #pragma unroll
        for (int j = 0; j < 4; j++) {
            float p0 = ex2(sacc[j][0] - mn0);
            float p1 = ex2(sacc[j][1] - mn0);
            float p2 = ex2(sacc[j][2] - mn1);
            float p3 = ex2(sacc[j][3] - mn1);
            ls0 += p0 + p1; ls1 += p2 + p3;
            __half h0 = __float2half_rn(p0), h1 = __float2half_rn(p1);
            __half h2 = __float2half_rn(p2), h3 = __float2half_rn(p3);
            int t = j >> 1, hf = (j & 1) * 2;
            phiA[t][hf + 0] = packh2(__half2float(h0), __half2float(h1));
            phiA[t][hf + 1] = packh2(__half2float(h2), __half2float(h3));
            ploA[t][hf + 0] = packh2(p0 - __half2float(h0), p1 - __half2float(h1));
            ploA[t][hf + 1] = packh2(p2 - __half2float(h2), p3 - __half2float(h3));
        }
        l0 += ls0; l1 += ls1;

        // ---- O += (Phi+Plo) . Vhi ----
        #pragma unroll
        for (int t = 0; t < 2; t++) {
            int rowb2 = t * 16 + rowb;
            uint32_t vhi[8][2];
            #pragma unroll
            for (int nc = 0; nc < 4; nc++) {
                uint32_t rr[4];
                ldmatrix_x4_trans(rr, Vst +
                    SW128((uint32_t)(rowb2 * 128 + nc * 32 + lc16)));
                vhi[nc * 2 + 0][0] = rr[0]; vhi[nc * 2 + 0][1] = rr[1];
                vhi[nc * 2 + 1][0] = rr[2]; vhi[nc * 2 + 1][1] = rr[3];
            }
            #pragma unroll
            for (int jn = 0; jn < 8; jn++) {
                mma_fp16(oacc[jn], phiA[t], vhi[jn]);   // Phi * Vhi
                mma_fp16(oacc[jn], ploA[t], vhi[jn]);   // Plo * Vhi
            }
        }
        __syncthreads();
    }

    l0 += __shfl_xor_sync(0xFFFFFFFF, l0, 1);
    l0 += __shfl_xor_sync(0xFFFFFFFF, l0, 2);
    l1 += __shfl_xor_sync(0xFFFFFFFF, l1, 1);
    l1 += __shfl_xor_sync(0xFFFFFFFF, l1, 2);
    float inv0 = 1.0f / l0, inv1 = 1.0f / l1;

    int r0 = qr0 + qw + gq;
    int r1 = r0 + 8;
    float* o0 = out + ((size_t)b * SEQL + r0) * DM + h_ * D;
    float* o1 = out + ((size_t)b * SEQL + r1) * DM + h_ * D;
    #pragma unroll
    for (int jn = 0; jn < 8; jn++) {
        int dc = jn * 8 + 2 * gt;
        *(float2*)(o0 + dc) = float2{oacc[jn][0] * inv0, oacc[jn][1] * inv0};
        *(float2*)(o1 + dc) = float2{oacc[jn][2] * inv1, oacc[jn][3] * inv1};
    }
}

// ---------------------------------------------------------------------------
extern "C" void kernel_launch(void* const* d_in, const int* in_sizes, int n_in,
                              void* d_out, int out_size)
{
    const float* X    = (const float*)d_in[0];
    const int*   mask = (const int*)  d_in[1];
    const float* Wq   = (const float*)d_in[2];
    const float* bq   = (const float*)d_in[3];
    const float* Wk   = (const float*)d_in[4];
    const float* bk   = (const float*)d_in[5];
    const float* Wv   = (const float*)d_in[6];
    const float* bv   = (const float*)d_in[7];

    __half* xp; cudaGetSymbolAddress((void**)&xp, g_Xp);
    __half* wh; cudaGetSymbolAddress((void**)&wh, g_Wh);

    // 1) fused split: X -> fp16 hi|lo, W -> fp16 hi
    split_all_kernel<<<R + 3 * DM, 256>>>(X, Wq, Wk, Wv, xp, wh);

    // 2) QKV projection (fp16 2-term) -> Q fp16 hi|lo, K/V fp16 hi
    cudaFuncSetAttribute(qkv_mma_kernel,
                         cudaFuncAttributeMaxDynamicSharedMemorySize, PROJ_SMEM);
    dim3 g1(DM / BN, R / BM, 3);                           // (8, 32, 3)
    qkv_mma_kernel<<<g1, 256, PROJ_SMEM>>>(bq, bk, bv);

    // 3) attention (fp16 2-term)
    cudaFuncSetAttribute(attn_mma_kernel,
                         cudaFuncAttributeMaxDynamicSharedMemorySize, ATT_SMEM);
    dim3 g2(SEQL / 128, NBH);
    attn_mma_kernel<<<g2, 256, ATT_SMEM>>>(mask, (float*)d_out);
}

// round 16
// speedup vs baseline: 1.5970x; 1.2555x over previous
#include <cuda_runtime.h>
#include <cuda_bf16.h>
#include <cuda_fp16.h>
#include <math.h>
#include <stdint.h>

#define BS   2
#define SEQL 2048
#define DM   1024
#define H    16
#define D    64
#define R    (BS*SEQL)   // 4096
#define NBH  (BS*H)      // 32

// Scratch (__device__ globals — no allocation).
// Q: fp16 hi|lo packed [bh][seq][128]: per 32-d block [32 hi][32 lo], row 256B.
// K/V: fp16 hi-only [bh][seq][64], row 128B.
__device__ __half g_Qs[(size_t)NBH*SEQL*128];
__device__ __half g_Ks[(size_t)NBH*SEQL*64];
__device__ __half g_Vs[(size_t)NBH*SEQL*64];
__device__ __half g_Xh[(size_t)R * DM];               // X hi-only fp16, 8 MB
__device__ __half g_Wh[(size_t)3 * DM * DM];          // W hi-only fp16, 6 MB

// ===========================================================================
// helpers
// ===========================================================================
__device__ __forceinline__ uint32_t smem_to_u32(const void* p) {
    uint32_t a;
    asm("{ .reg .u64 t; cvta.to.shared.u64 t, %1; cvt.u32.u64 %0, t; }" : "=r"(a) : "l"(p));
    return a;
}
#define SW128(off) ((off) ^ (((off) >> 3) & 0x70))     // 128B rows
#define SWZ256(off) ((off) ^ (((off) >> 4) & 0x70))    // 256B rows

#define CP_ASYNC16(saddr, gptr) \
    asm volatile("cp.async.cg.shared.global [%0], [%1], 16;" :: "r"(saddr), "l"(gptr))
#define CP_COMMIT() asm volatile("cp.async.commit_group;" ::: "memory")
#define CP_WAIT1()  asm volatile("cp.async.wait_group 1;" ::: "memory")
#define CP_WAIT0()  asm volatile("cp.async.wait_group 0;" ::: "memory")

__device__ __forceinline__ void ldmatrix_x4(uint32_t* r, uint32_t addr) {
    asm volatile("ldmatrix.sync.aligned.m8n8.x4.shared.b16 {%0,%1,%2,%3}, [%4];"
        : "=r"(r[0]), "=r"(r[1]), "=r"(r[2]), "=r"(r[3]) : "r"(addr));
}
__device__ __forceinline__ void ldmatrix_x4_trans(uint32_t* r, uint32_t addr) {
    asm volatile("ldmatrix.sync.aligned.m8n8.x4.trans.shared.b16 {%0,%1,%2,%3}, [%4];"
        : "=r"(r[0]), "=r"(r[1]), "=r"(r[2]), "=r"(r[3]) : "r"(addr));
}
__device__ __forceinline__ void mma_fp16(float* d, const uint32_t* a, const uint32_t* b) {
    asm volatile(
        "mma.sync.aligned.m16n8k16.row.col.f32.f16.f16.f32 "
        "{%0,%1,%2,%3}, {%4,%5,%6,%7}, {%8,%9}, {%0,%1,%2,%3};"
        : "+f"(d[0]), "+f"(d[1]), "+f"(d[2]), "+f"(d[3])
        : "r"(a[0]), "r"(a[1]), "r"(a[2]), "r"(a[3]), "r"(b[0]), "r"(b[1]));
}
__device__ __forceinline__ float ex2(float x) {
    float y; asm("ex2.approx.ftz.f32 %0, %1;" : "=f"(y) : "f"(x)); return y;
}
__device__ __forceinline__ uint32_t packh2(float a, float b) {
    __half2 t = __floats2half2_rn(a, b);
    return *(uint32_t*)&t;
}
#define LOG2E 1.4426950408889634f

// ===========================================================================
// Fused split kernel: all rows (X then Wq,Wk,Wv) -> fp16 hi-only, k-major.
// ===========================================================================
__global__ __launch_bounds__(256) void split_all_kernel(
    const float* __restrict__ X,
    const float* __restrict__ Wq, const float* __restrict__ Wk,
    const float* __restrict__ Wv,
    __half* __restrict__ Xh, __half* __restrict__ Wh)
{
    int blk = blockIdx.x;
    int k = threadIdx.x * 4;
    const float* src;
    __half* dstrow;
    if (blk < R) {
        src = X + (size_t)blk * DM;
        dstrow = Xh + (size_t)blk * DM;
    } else {
        int w = blk - R;
        int z = w >> 10;
        int row = w & 1023;
        const float* ws = (z == 0) ? Wq : (z == 1) ? Wk : Wv;
        src = ws + (size_t)row * DM;
        dstrow = Wh + ((size_t)z * DM + row) * DM;
    }
    float4 v = *(const float4*)(src + k);
    *(__half2*)(dstrow + k)     = __half2{__float2half_rn(v.x), __float2half_rn(v.y)};
    *(__half2*)(dstrow + k + 2) = __half2{__float2half_rn(v.z), __float2half_rn(v.w)};
}

// ===========================================================================
// Projection GEMM via mma.sync fp16, single term: C = Xhi . Whi^T.
// CTA 128x128, warp tile 64x32 (8 warps: 2M x 4N), BK=64 orig k per stage.
// A and B stages both 128 rows x 128B (SW128), 16KB each.
// 2-stage cp.async (proven schedule). Epilogue: Q fp16 hi|lo, K/V fp16 hi.
// ===========================================================================
#define BM 128
#define BN 128
#define NK (DM/64)                   // 16 iterations
#define STG_BYTES 32768              // A 16KB + B 16KB
#define PROJ_SMEM (2 * STG_BYTES)    // 64KB

__device__ __forceinline__ void proj_load_stage(
    uint32_t sbase, int stage, int kt,
    const char* gA, const char* gB, int tid)
{
    uint32_t sa = sbase + stage * STG_BYTES;
    uint32_t sb = sa + 16384;
    const char* a = gA + (size_t)kt * 128;
    const char* b = gB + (size_t)kt * 128;
    int row = tid >> 3, c = tid & 7;
    #pragma unroll
    for (int p = 0; p < 4; p++) {
        uint32_t off = SW128((uint32_t)((row + p * 32) * 128 + c * 16));
        CP_ASYNC16(sa + off, a + (size_t)(row + p * 32) * 2048 + c * 16);
        CP_ASYNC16(sb + off, b + (size_t)(row + p * 32) * 2048 + c * 16);
    }
}

__global__ __launch_bounds__(256, 2) void qkv_mma_kernel(
    const float* __restrict__ bq, const float* __restrict__ bk,
    const float* __restrict__ bv)
{
    extern __shared__ char smem[];
    const uint32_t sbase = smem_to_u32(smem);
    const int tid  = threadIdx.x;
    const int wid  = tid >> 5;
    const int lane = tid & 31;
    const int z    = blockIdx.z;

    const float* bias; __half* Outs; float scale;
    if (z == 0)      { bias = bq; Outs = g_Qs; scale = 0.125f; }
    else if (z == 1) { bias = bk; Outs = g_Ks; scale = 1.0f;   }
    else             { bias = bv; Outs = g_Vs; scale = 1.0f;   }

    const int n0 = blockIdx.x * BN;
    const int m0 = blockIdx.y * BM;

    const char* gA = (const char*)g_Xh + (size_t)m0 * 2048;
    const char* gB = (const char*)(g_Wh + (size_t)z * DM * DM) + (size_t)n0 * 2048;

    proj_load_stage(sbase, 0, 0, gA, gB, tid);
    CP_COMMIT();

    const int wm = (wid & 1) * 64;
    const int wn = (wid >> 1) * 32;
    float acc[4][4][4];
    #pragma unroll
    for (int f = 0; f < 4; f++)
        #pragma unroll
        for (int g = 0; g < 4; g++)
            #pragma unroll
            for (int i = 0; i < 4; i++) acc[f][g][i] = 0.0f;

    const int lrow16 = lane & 15;
    const int lc16   = (lane >> 4) << 4;
    const uint32_t arow_base = (uint32_t)((wm + lrow16) * 128) + (uint32_t)lc16;
    const uint32_t brow_base = (uint32_t)((wn + lrow16) * 128) + (uint32_t)lc16;

    for (int kt = 0; kt < NK; kt++) {
        if (kt + 1 < NK) {
            proj_load_stage(sbase, (kt + 1) & 1, kt + 1, gA, gB, tid);
            CP_COMMIT();
            CP_WAIT1();
        } else {
            CP_WAIT0();
        }
        __syncthreads();

        const uint32_t abase = sbase + (kt & 1) * STG_BYTES;
        const uint32_t bbase = abase + 16384;

        #pragma unroll
        for (int kh = 0; kh < 4; kh++) {      // 4 x k16 per stage (64 k)
            uint32_t bf[4][2];
            #pragma unroll
            for (int g2 = 0; g2 < 2; g2++) {
                uint32_t rr[4];
                ldmatrix_x4(rr, bbase +
                    SW128(brow_base + (uint32_t)(g2 * 16 * 128 + kh * 32)));
                bf[g2 * 2 + 0][0] = rr[0]; bf[g2 * 2 + 0][1] = rr[2];
                bf[g2 * 2 + 1][0] = rr[1]; bf[g2 * 2 + 1][1] = rr[3];
            }
            #pragma unroll
            for (int f = 0; f < 4; f++) {
                uint32_t af[4];
                ldmatrix_x4(af, abase +
                    SW128(arow_base + (uint32_t)(f * 16 * 128 + kh * 32)));
                #pragma unroll
                for (int g = 0; g < 4; g++)
                    mma_fp16(acc[f][g], af, bf[g]);    // xhi * whi
            }
        }
        __syncthreads();
    }

    // Epilogue: bias + scale; Q -> fp16 hi|lo, K/V -> fp16 hi-only.
    const int gq = lane >> 2;
    const int gt = lane & 3;
    #pragma unroll
    for (int f = 0; f < 4; f++) {
        #pragma unroll
        for (int g = 0; g < 4; g++) {
            int col = n0 + wn + g * 8 + 2 * gt;
            int h_  = col >> 6;
            int dd  = col & 63;
            float b0 = __ldg(&bias[col]), b1 = __ldg(&bias[col + 1]);
            #pragma unroll
            for (int half = 0; half < 2; half++) {
                int m_abs = m0 + wm + f * 16 + gq + half * 8;
                int bb = m_abs >> 11;
                int ss = m_abs & (SEQL - 1);
                float vx = (acc[f][g][half * 2 + 0] + b0) * scale;
                float vy = (acc[f][g][half * 2 + 1] + b1) * scale;
                __half hx = __float2half_rn(vx);
                __half hy = __float2half_rn(vy);
                if (z == 0) {
                    int dblk = dd >> 5, pos = dd & 31;
                    __half lx = __float2half_rn(vx - __half2float(hx));
                    __half ly = __float2half_rn(vy - __half2float(hy));
                    size_t base = ((size_t)((bb * H + h_) * SEQL + ss)) * 128 + dblk * 64 + pos;
                    *(__half2*)(Outs + base)      = __half2{hx, hy};
                    *(__half2*)(Outs + base + 32) = __half2{lx, ly};
                } else {
                    size_t base = ((size_t)((bb * H + h_) * SEQL + ss)) * 64 + dd;
                    *(__half2*)(Outs + base) = __half2{hx, hy};
                }
            }
        }
    }
}

// ===========================================================================
// Attention via mma.sync fp16 2-term: S = (Qhi+Qlo).Khi^T, O = (Phi+Plo).Vhi.
// (unchanged from R15 — proven)
// ===========================================================================
#define AKT 32
#define ANIT (SEQL/AKT)      // 64
#define SQ_OFF 0
#define SK_OFF 32768
#define SV_OFF 40960
#define SB_OFF 49152
#define ATT_SMEM 57344

__global__ __launch_bounds__(256, 1) void attn_mma_kernel(
    const int* __restrict__ mask, float* __restrict__ out)
{
    extern __shared__ char smem[];
    const uint32_t sbase = smem_to_u32(smem);
    const uint32_t sQ = sbase + SQ_OFF;
    const uint32_t sK = sbase + SK_OFF;
    const uint32_t sV = sbase + SV_OFF;
    float* sbias = (float*)(smem + SB_OFF);

    const int tid  = threadIdx.x;
    const int wid  = tid >> 5;
    const int lane = tid & 31;
    const int gq   = lane >> 2;
    const int gt   = lane & 3;
    const int bh   = blockIdx.y;
    const int b    = bh >> 4;
    const int h_   = bh & 15;
    const int qr0  = blockIdx.x * 128;
    const int qw   = wid * 16;

    const char* Qg = (const char*)(g_Qs + ((size_t)bh * SEQL + qr0) * 128);
    const char* Kg = (const char*)(g_Ks + (size_t)bh * SEQL * 64);
    const char* Vg = (const char*)(g_Vs + (size_t)bh * SEQL * 64);

    {
        #pragma unroll
        for (int i = 0; i < 8; i++) {
            int idx = tid + i * 256;
            int row = idx >> 4, c = idx & 15;
            CP_ASYNC16(sQ + SWZ256((uint32_t)(row * 256 + c * 16)),
                       Qg + (size_t)row * 256 + c * 16);
        }
        {
            int row = tid >> 3, c = tid & 7;
            uint32_t off = SW128((uint32_t)(row * 128 + c * 16));
            CP_ASYNC16(sK + off, Kg + (size_t)row * 128 + c * 16);
            CP_ASYNC16(sV + off, Vg + (size_t)row * 128 + c * 16);
        }
        CP_COMMIT();
        #pragma unroll
        for (int i = 0; i < 8; i++) {
            int j = tid + i * 256;
            sbias[j] = mask[b * SEQL + j] ? 0.0f : -2.6e29f;
        }
    }

    uint32_t qf[2][4][4];
    float oacc[8][4];
    #pragma unroll
    for (int j = 0; j < 8; j++)
        #pragma unroll
        for (int i = 0; i < 4; i++) oacc[j][i] = 0.0f;
    float m0 = -INFINITY, m1 = -INFINITY, l0 = 0.0f, l1 = 0.0f;

    const int rowb = lane & 15;
    const int lc16 = (lane >> 4) << 4;

    for (int kt = 0; kt < ANIT; kt++) {
        if (kt + 1 < ANIT) {
            uint32_t dstK = sK + ((kt + 1) & 1) * 4096;
            uint32_t dstV = sV + ((kt + 1) & 1) * 4096;
            const char* kg = Kg + (size_t)(kt + 1) * AKT * 128;
            const char* vg = Vg + (size_t)(kt + 1) * AKT * 128;
            {
                int row = tid >> 3, c = tid & 7;
                uint32_t off = SW128((uint32_t)(row * 128 + c * 16));
                CP_ASYNC16(dstK + off, kg + (size_t)row * 128 + c * 16);
                CP_ASYNC16(dstV + off, vg + (size_t)row * 128 + c * 16);
            }
            CP_COMMIT();
            CP_WAIT1();
        } else {
            CP_WAIT0();
        }
        __syncthreads();

        if (kt == 0) {
            #pragma unroll
            for (int hl = 0; hl < 2; hl++)
                #pragma unroll
                for (int s = 0; s < 4; s++) {
                    int row = qw + rowb;
                    int cb  = (s >> 1) * 128 + hl * 64 + (s & 1) * 32 + lc16;
                    ldmatrix_x4(qf[hl][s], sQ + SWZ256((uint32_t)(row * 256 + cb)));
                }
        }

        const uint32_t Kst = sK + (kt & 1) * 4096;
        const uint32_t Vst = sV + (kt & 1) * 4096;

        float sacc[4][4];
        #pragma unroll
        for (int j = 0; j < 4; j++)
            #pragma unroll
            for (int i = 0; i < 4; i++) sacc[j][i] = 0.0f;

        #pragma unroll
        for (int s = 0; s < 4; s++) {
            uint32_t khi[4][2];
            #pragma unroll
            for (int g2 = 0; g2 < 2; g2++) {
                uint32_t rr[4];
                ldmatrix_x4(rr, Kst +
                    SW128((uint32_t)((g2 * 16 + rowb) * 128 + s * 32 + lc16)));
                khi[g2 * 2 + 0][0] = rr[0]; khi[g2 * 2 + 0][1] = rr[2];
                khi[g2 * 2 + 1][0] = rr[1]; khi[g2 * 2 + 1][1] = rr[3];
            }
            #pragma unroll
            for (int j = 0; j < 4; j++) {
                mma_fp16(sacc[j], qf[0][s], khi[j]);
                mma_fp16(sacc[j], qf[1][s], khi[j]);
            }
        }

        float mx0 = -INFINITY, mx1 = -INFINITY;
        #pragma unroll
        for (int j = 0; j < 4; j++) {
            float2 bb = *(float2*)&sbias[kt * AKT + j * 8 + 2 * gt];
            sacc[j][0] = fmaf(sacc[j][0], LOG2E, bb.x);
            sacc[j][1] = fmaf(sacc[j][1], LOG2E, bb.y);
            sacc[j][2] = fmaf(sacc[j][2], LOG2E, bb.x);
            sacc[j][3] = fmaf(sacc[j][3], LOG2E, bb.y);
            mx0 = fmaxf(mx0, fmaxf(sacc[j][0], sacc[j][1]));
            mx1 = fmaxf(mx1, fmaxf(sacc[j][2], sacc[j][3]));
        }
        mx0 = fmaxf(mx0, __shfl_xor_sync(0xFFFFFFFF, mx0, 1));
        mx0 = fmaxf(mx0, __shfl_xor_sync(0xFFFFFFFF, mx0, 2));
        mx1 = fmaxf(mx1, __shfl_xor_sync(0xFFFFFFFF, mx1, 1));
        mx1 = fmaxf(mx1, __shfl_xor_sync(0xFFFFFFFF, mx1, 2));
        float mn0 = fmaxf(m0, mx0), mn1 = fmaxf(m1, mx1);
        float c0 = ex2(m0 - mn0), c1 = ex2(m1 - mn1);
        m0 = mn0; m1 = mn1;
        l0 *= c0;  l1 *= c1;
        #pragma unroll
        for (int j = 0; j < 8; j++) {
            oacc[j][0] *= c0; oacc[j][1] *= c0;
            oacc[j][2] *= c1; oacc[j][3] *= c1;
        }

        uint32_t phiA[2][4], ploA[2][4];
        float ls0 = 0.0f, ls1 = 0.0f;
        #pragma unroll
        for (int j = 0; j < 4; j++) {
            float p0 = ex2(sacc[j][0] - mn0);
            float p1 = ex2(sacc[j][1] - mn0);
            float p2 = ex2(sacc[j][2] - mn1);
            float p3 = ex2(sacc[j][3] - mn1);
            ls0 += p0 + p1; ls1 += p2 + p3;
            __half h0 = __float2half_rn(p0), h1 = __float2half_rn(p1);
            __half h2 = __float2half_rn(p2), h3 = __float2half_rn(p3);
            int t = j >> 1, hf = (j & 1) * 2;
            phiA[t][hf + 0] = packh2(__half2float(h0), __half2float(h1));
            phiA[t][hf + 1] = packh2(__half2float(h2), __half2float(h3));
            ploA[t][hf + 0] = packh2(p0 - __half2float(h0), p1 - __half2float(h1));
            ploA[t][hf + 1] = packh2(p2 - __half2float(h2), p3 - __half2float(h3));
        }
        l0 += ls0; l1 += ls1;

        #pragma unroll
        for (int t = 0; t < 2; t++) {
            int rowb2 = t * 16 + rowb;
            uint32_t vhi[8][2];
            #pragma unroll
            for (int nc = 0; nc < 4; nc++) {
                uint32_t rr[4];
                ldmatrix_x4_trans(rr, Vst +
                    SW128((uint32_t)(rowb2 * 128 + nc * 32 + lc16)));
                vhi[nc * 2 + 0][0] = rr[0]; vhi[nc * 2 + 0][1] = rr[1];
                vhi[nc * 2 + 1][0] = rr[2]; vhi[nc * 2 + 1][1] = rr[3];
            }
            #pragma unroll
            for (int jn = 0; jn < 8; jn++) {
                mma_fp16(oacc[jn], phiA[t], vhi[jn]);
                mma_fp16(oacc[jn], ploA[t], vhi[jn]);
            }
        }
        __syncthreads();
    }

    l0 += __shfl_xor_sync(0xFFFFFFFF, l0, 1);
    l0 += __shfl_xor_sync(0xFFFFFFFF, l0, 2);
    l1 += __shfl_xor_sync(0xFFFFFFFF, l1, 1);
    l1 += __shfl_xor_sync(0xFFFFFFFF, l1, 2);
    float inv0 = 1.0f / l0, inv1 = 1.0f / l1;

    int r0 = qr0 + qw + gq;
    int r1 = r0 + 8;
    float* o0 = out + ((size_t)b * SEQL + r0) * DM + h_ * D;
    float* o1 = out + ((size_t)b * SEQL + r1) * DM + h_ * D;
    #pragma unroll
    for (int jn = 0; jn < 8; jn++) {
        int dc = jn * 8 + 2 * gt;
        *(float2*)(o0 + dc) = float2{oacc[jn][0] * inv0, oacc[jn][1] * inv0};
        *(float2*)(o1 + dc) = float2{oacc[jn][2] * inv1, oacc[jn][3] * inv1};
    }
}

// ---------------------------------------------------------------------------
extern "C" void kernel_launch(void* const* d_in, const int* in_sizes, int n_in,
                              void* d_out, int out_size)
{
    const float* X    = (const float*)d_in[0];
    const int*   mask = (const int*)  d_in[1];
    const float* Wq   = (const float*)d_in[2];
    const float* bq   = (const float*)d_in[3];
    const float* Wk   = (const float*)d_in[4];
    const float* bk   = (const float*)d_in[5];
    const float* Wv   = (const float*)d_in[6];
    const float* bv   = (const float*)d_in[7];

    __half* xh; cudaGetSymbolAddress((void**)&xh, g_Xh);
    __half* wh; cudaGetSymbolAddress((void**)&wh, g_Wh);

    // 1) fused split: X and W -> fp16 hi-only
    split_all_kernel<<<R + 3 * DM, 256>>>(X, Wq, Wk, Wv, xh, wh);

    // 2) QKV projection (fp16 1-term) -> Q fp16 hi|lo, K/V fp16 hi
    cudaFuncSetAttribute(qkv_mma_kernel,
                         cudaFuncAttributeMaxDynamicSharedMemorySize, PROJ_SMEM);
    dim3 g1(DM / BN, R / BM, 3);                           // (8, 32, 3)
    qkv_mma_kernel<<<g1, 256, PROJ_SMEM>>>(bq, bk, bv);

    // 3) attention (fp16 2-term, unchanged)
    cudaFuncSetAttribute(attn_mma_kernel,
                         cudaFuncAttributeMaxDynamicSharedMemorySize, ATT_SMEM);
    dim3 g2(SEQL / 128, NBH);
    attn_mma_kernel<<<g2, 256, ATT_SMEM>>>(mask, (float*)d_out);
}

// round 17
// speedup vs baseline: 1.8430x; 1.1541x over previous
#include <cuda_runtime.h>
#include <cuda_bf16.h>
#include <cuda_fp16.h>
#include <math.h>
#include <stdint.h>

#define BS   2
#define SEQL 2048
#define DM   1024
#define H    16
#define D    64
#define R    (BS*SEQL)   // 4096
#define NBH  (BS*H)      // 32

// Scratch (__device__ globals — no allocation).
// Q: fp16 hi|lo packed [bh][seq][128]: per 32-d block [32 hi][32 lo], row 256B.
// K/V: fp16 hi-only [bh][seq][64], row 128B.
__device__ __half g_Qs[(size_t)NBH*SEQL*128];
__device__ __half g_Ks[(size_t)NBH*SEQL*64];
__device__ __half g_Vs[(size_t)NBH*SEQL*64];
__device__ __half g_Xh[(size_t)R * DM];               // X hi-only fp16, 8 MB
__device__ __half g_Wh[(size_t)3 * DM * DM];          // W hi-only fp16, 6 MB

// ===========================================================================
// helpers
// ===========================================================================
__device__ __forceinline__ uint32_t smem_to_u32(const void* p) {
    uint32_t a;
    asm("{ .reg .u64 t; cvta.to.shared.u64 t, %1; cvt.u32.u64 %0, t; }" : "=r"(a) : "l"(p));
    return a;
}
#define SW128(off) ((off) ^ (((off) >> 3) & 0x70))     // 128B rows
#define SWZ256(off) ((off) ^ (((off) >> 4) & 0x70))    // 256B rows

#define CP_ASYNC16(saddr, gptr) \
    asm volatile("cp.async.cg.shared.global [%0], [%1], 16;" :: "r"(saddr), "l"(gptr))
#define CP_COMMIT() asm volatile("cp.async.commit_group;" ::: "memory")
#define CP_WAIT1()  asm volatile("cp.async.wait_group 1;" ::: "memory")
#define CP_WAIT0()  asm volatile("cp.async.wait_group 0;" ::: "memory")

__device__ __forceinline__ void ldmatrix_x4(uint32_t* r, uint32_t addr) {
    asm volatile("ldmatrix.sync.aligned.m8n8.x4.shared.b16 {%0,%1,%2,%3}, [%4];"
        : "=r"(r[0]), "=r"(r[1]), "=r"(r[2]), "=r"(r[3]) : "r"(addr));
}
__device__ __forceinline__ void ldmatrix_x4_trans(uint32_t* r, uint32_t addr) {
    asm volatile("ldmatrix.sync.aligned.m8n8.x4.trans.shared.b16 {%0,%1,%2,%3}, [%4];"
        : "=r"(r[0]), "=r"(r[1]), "=r"(r[2]), "=r"(r[3]) : "r"(addr));
}
__device__ __forceinline__ void mma_fp16(float* d, const uint32_t* a, const uint32_t* b) {
    asm volatile(
        "mma.sync.aligned.m16n8k16.row.col.f32.f16.f16.f32 "
        "{%0,%1,%2,%3}, {%4,%5,%6,%7}, {%8,%9}, {%0,%1,%2,%3};"
        : "+f"(d[0]), "+f"(d[1]), "+f"(d[2]), "+f"(d[3])
        : "r"(a[0]), "r"(a[1]), "r"(a[2]), "r"(a[3]), "r"(b[0]), "r"(b[1]));
}
__device__ __forceinline__ float ex2(float x) {
    float y; asm("ex2.approx.ftz.f32 %0, %1;" : "=f"(y) : "f"(x)); return y;
}
__device__ __forceinline__ uint32_t packh2(float a, float b) {
    __half2 t = __floats2half2_rn(a, b);
    return *(uint32_t*)&t;
}
#define LOG2E 1.4426950408889634f

// ===========================================================================
// Fused split kernel: all rows (X then Wq,Wk,Wv) -> fp16 hi-only, k-major.
// ===========================================================================
__global__ __launch_bounds__(256) void split_all_kernel(
    const float* __restrict__ X,
    const float* __restrict__ Wq, const float* __restrict__ Wk,
    const float* __restrict__ Wv,
    __half* __restrict__ Xh, __half* __restrict__ Wh)
{
    int blk = blockIdx.x;
    int k = threadIdx.x * 4;
    const float* src;
    __half* dstrow;
    if (blk < R) {
        src = X + (size_t)blk * DM;
        dstrow = Xh + (size_t)blk * DM;
    } else {
        int w = blk - R;
        int z = w >> 10;
        int row = w & 1023;
        const float* ws = (z == 0) ? Wq : (z == 1) ? Wk : Wv;
        src = ws + (size_t)row * DM;
        dstrow = Wh + ((size_t)z * DM + row) * DM;
    }
    float4 v = *(const float4*)(src + k);
    *(__half2*)(dstrow + k)     = __half2{__float2half_rn(v.x), __float2half_rn(v.y)};
    *(__half2*)(dstrow + k + 2) = __half2{__float2half_rn(v.z), __float2half_rn(v.w)};
}

// ===========================================================================
// Projection GEMM via mma.sync fp16, single term: C = Xhi . Whi^T.
// (unchanged from R16 — proven)
// ===========================================================================
#define BM 128
#define BN 128
#define NK (DM/64)                   // 16 iterations
#define STG_BYTES 32768              // A 16KB + B 16KB
#define PROJ_SMEM (2 * STG_BYTES)    // 64KB

__device__ __forceinline__ void proj_load_stage(
    uint32_t sbase, int stage, int kt,
    const char* gA, const char* gB, int tid)
{
    uint32_t sa = sbase + stage * STG_BYTES;
    uint32_t sb = sa + 16384;
    const char* a = gA + (size_t)kt * 128;
    const char* b = gB + (size_t)kt * 128;
    int row = tid >> 3, c = tid & 7;
    #pragma unroll
    for (int p = 0; p < 4; p++) {
        uint32_t off = SW128((uint32_t)((row + p * 32) * 128 + c * 16));
        CP_ASYNC16(sa + off, a + (size_t)(row + p * 32) * 2048 + c * 16);
        CP_ASYNC16(sb + off, b + (size_t)(row + p * 32) * 2048 + c * 16);
    }
}

__global__ __launch_bounds__(256, 2) void qkv_mma_kernel(
    const float* __restrict__ bq, const float* __restrict__ bk,
    const float* __restrict__ bv)
{
    extern __shared__ char smem[];
    const uint32_t sbase = smem_to_u32(smem);
    const int tid  = threadIdx.x;
    const int wid  = tid >> 5;
    const int lane = tid & 31;
    const int z    = blockIdx.z;

    const float* bias; __half* Outs; float scale;
    if (z == 0)      { bias = bq; Outs = g_Qs; scale = 0.125f; }
    else if (z == 1) { bias = bk; Outs = g_Ks; scale = 1.0f;   }
    else             { bias = bv; Outs = g_Vs; scale = 1.0f;   }

    const int n0 = blockIdx.x * BN;
    const int m0 = blockIdx.y * BM;

    const char* gA = (const char*)g_Xh + (size_t)m0 * 2048;
    const char* gB = (const char*)(g_Wh + (size_t)z * DM * DM) + (size_t)n0 * 2048;

    proj_load_stage(sbase, 0, 0, gA, gB, tid);
    CP_COMMIT();

    const int wm = (wid & 1) * 64;
    const int wn = (wid >> 1) * 32;
    float acc[4][4][4];
    #pragma unroll
    for (int f = 0; f < 4; f++)
        #pragma unroll
        for (int g = 0; g < 4; g++)
            #pragma unroll
            for (int i = 0; i < 4; i++) acc[f][g][i] = 0.0f;

    const int lrow16 = lane & 15;
    const int lc16   = (lane >> 4) << 4;
    const uint32_t arow_base = (uint32_t)((wm + lrow16) * 128) + (uint32_t)lc16;
    const uint32_t brow_base = (uint32_t)((wn + lrow16) * 128) + (uint32_t)lc16;

    for (int kt = 0; kt < NK; kt++) {
        if (kt + 1 < NK) {
            proj_load_stage(sbase, (kt + 1) & 1, kt + 1, gA, gB, tid);
            CP_COMMIT();
            CP_WAIT1();
        } else {
            CP_WAIT0();
        }
        __syncthreads();

        const uint32_t abase = sbase + (kt & 1) * STG_BYTES;
        const uint32_t bbase = abase + 16384;

        #pragma unroll
        for (int kh = 0; kh < 4; kh++) {      // 4 x k16 per stage (64 k)
            uint32_t bf[4][2];
            #pragma unroll
            for (int g2 = 0; g2 < 2; g2++) {
                uint32_t rr[4];
                ldmatrix_x4(rr, bbase +
                    SW128(brow_base + (uint32_t)(g2 * 16 * 128 + kh * 32)));
                bf[g2 * 2 + 0][0] = rr[0]; bf[g2 * 2 + 0][1] = rr[2];
                bf[g2 * 2 + 1][0] = rr[1]; bf[g2 * 2 + 1][1] = rr[3];
            }
            #pragma unroll
            for (int f = 0; f < 4; f++) {
                uint32_t af[4];
                ldmatrix_x4(af, abase +
                    SW128(arow_base + (uint32_t)(f * 16 * 128 + kh * 32)));
                #pragma unroll
                for (int g = 0; g < 4; g++)
                    mma_fp16(acc[f][g], af, bf[g]);    // xhi * whi
            }
        }
        __syncthreads();
    }

    // Epilogue: bias + scale; Q -> fp16 hi|lo, K/V -> fp16 hi-only.
    const int gq = lane >> 2;
    const int gt = lane & 3;
    #pragma unroll
    for (int f = 0; f < 4; f++) {
        #pragma unroll
        for (int g = 0; g < 4; g++) {
            int col = n0 + wn + g * 8 + 2 * gt;
            int h_  = col >> 6;
            int dd  = col & 63;
            float b0 = __ldg(&bias[col]), b1 = __ldg(&bias[col + 1]);
            #pragma unroll
            for (int half = 0; half < 2; half++) {
                int m_abs = m0 + wm + f * 16 + gq + half * 8;
                int bb = m_abs >> 11;
                int ss = m_abs & (SEQL - 1);
                float vx = (acc[f][g][half * 2 + 0] + b0) * scale;
                float vy = (acc[f][g][half * 2 + 1] + b1) * scale;
                __half hx = __float2half_rn(vx);
                __half hy = __float2half_rn(vy);
                if (z == 0) {
                    int dblk = dd >> 5, pos = dd & 31;
                    __half lx = __float2half_rn(vx - __half2float(hx));
                    __half ly = __float2half_rn(vy - __half2float(hy));
                    size_t base = ((size_t)((bb * H + h_) * SEQL + ss)) * 128 + dblk * 64 + pos;
                    *(__half2*)(Outs + base)      = __half2{hx, hy};
                    *(__half2*)(Outs + base + 32) = __half2{lx, ly};
                } else {
                    size_t base = ((size_t)((bb * H + h_) * SEQL + ss)) * 64 + dd;
                    *(__half2*)(Outs + base) = __half2{hx, hy};
                }
            }
        }
    }
}

// ===========================================================================
// Attention via mma.sync fp16: S = (Qhi+Qlo).Khi^T (2-term), O = Phi.Vhi (1-term).
// CTA: 256 thr (8 warps), 128 q-rows of one bh; KT=32 keys/iter, 64 iters.
// SMEM: Q 32KB | K 2x4KB | V 2x4KB | bias 8KB = 56KB.
// ===========================================================================
#define AKT 32
#define ANIT (SEQL/AKT)      // 64
#define SQ_OFF 0
#define SK_OFF 32768
#define SV_OFF 40960
#define SB_OFF 49152
#define ATT_SMEM 57344

__global__ __launch_bounds__(256, 1) void attn_mma_kernel(
    const int* __restrict__ mask, float* __restrict__ out)
{
    extern __shared__ char smem[];
    const uint32_t sbase = smem_to_u32(smem);
    const uint32_t sQ = sbase + SQ_OFF;
    const uint32_t sK = sbase + SK_OFF;
    const uint32_t sV = sbase + SV_OFF;
    float* sbias = (float*)(smem + SB_OFF);

    const int tid  = threadIdx.x;
    const int wid  = tid >> 5;
    const int lane = tid & 31;
    const int gq   = lane >> 2;
    const int gt   = lane & 3;
    const int bh   = blockIdx.y;
    const int b    = bh >> 4;
    const int h_   = bh & 15;
    const int qr0  = blockIdx.x * 128;
    const int qw   = wid * 16;

    const char* Qg = (const char*)(g_Qs + ((size_t)bh * SEQL + qr0) * 128);
    const char* Kg = (const char*)(g_Ks + (size_t)bh * SEQL * 64);
    const char* Vg = (const char*)(g_Vs + (size_t)bh * SEQL * 64);

    {
        #pragma unroll
        for (int i = 0; i < 8; i++) {
            int idx = tid + i * 256;
            int row = idx >> 4, c = idx & 15;
            CP_ASYNC16(sQ + SWZ256((uint32_t)(row * 256 + c * 16)),
                       Qg + (size_t)row * 256 + c * 16);
        }
        {
            int row = tid >> 3, c = tid & 7;
            uint32_t off = SW128((uint32_t)(row * 128 + c * 16));
            CP_ASYNC16(sK + off, Kg + (size_t)row * 128 + c * 16);
            CP_ASYNC16(sV + off, Vg + (size_t)row * 128 + c * 16);
        }
        CP_COMMIT();
        #pragma unroll
        for (int i = 0; i < 8; i++) {
            int j = tid + i * 256;
            sbias[j] = mask[b * SEQL + j] ? 0.0f : -2.6e29f;
        }
    }

    uint32_t qf[2][4][4];
    float oacc[8][4];
    #pragma unroll
    for (int j = 0; j < 8; j++)
        #pragma unroll
        for (int i = 0; i < 4; i++) oacc[j][i] = 0.0f;
    float m0 = -INFINITY, m1 = -INFINITY, l0 = 0.0f, l1 = 0.0f;

    const int rowb = lane & 15;
    const int lc16 = (lane >> 4) << 4;

    for (int kt = 0; kt < ANIT; kt++) {
        if (kt + 1 < ANIT) {
            uint32_t dstK = sK + ((kt + 1) & 1) * 4096;
            uint32_t dstV = sV + ((kt + 1) & 1) * 4096;
            const char* kg = Kg + (size_t)(kt + 1) * AKT * 128;
            const char* vg = Vg + (size_t)(kt + 1) * AKT * 128;
            {
                int row = tid >> 3, c = tid & 7;
                uint32_t off = SW128((uint32_t)(row * 128 + c * 16));
                CP_ASYNC16(dstK + off, kg + (size_t)row * 128 + c * 16);
                CP_ASYNC16(dstV + off, vg + (size_t)row * 128 + c * 16);
            }
            CP_COMMIT();
            CP_WAIT1();
        } else {
            CP_WAIT0();
        }
        __syncthreads();

        if (kt == 0) {
            #pragma unroll
            for (int hl = 0; hl < 2; hl++)
                #pragma unroll
                for (int s = 0; s < 4; s++) {
                    int row = qw + rowb;
                    int cb  = (s >> 1) * 128 + hl * 64 + (s & 1) * 32 + lc16;
                    ldmatrix_x4(qf[hl][s], sQ + SWZ256((uint32_t)(row * 256 + cb)));
                }
        }

        const uint32_t Kst = sK + (kt & 1) * 4096;
        const uint32_t Vst = sV + (kt & 1) * 4096;

        // ---- S = (Qhi+Qlo) . Khi^T ----
        float sacc[4][4];
        #pragma unroll
        for (int j = 0; j < 4; j++)
            #pragma unroll
            for (int i = 0; i < 4; i++) sacc[j][i] = 0.0f;

        #pragma unroll
        for (int s = 0; s < 4; s++) {
            uint32_t khi[4][2];
            #pragma unroll
            for (int g2 = 0; g2 < 2; g2++) {
                uint32_t rr[4];
                ldmatrix_x4(rr, Kst +
                    SW128((uint32_t)((g2 * 16 + rowb) * 128 + s * 32 + lc16)));
                khi[g2 * 2 + 0][0] = rr[0]; khi[g2 * 2 + 0][1] = rr[2];
                khi[g2 * 2 + 1][0] = rr[1]; khi[g2 * 2 + 1][1] = rr[3];
            }
            #pragma unroll
            for (int j = 0; j < 4; j++) {
                mma_fp16(sacc[j], qf[0][s], khi[j]);
                mma_fp16(sacc[j], qf[1][s], khi[j]);
            }
        }

        // ---- mask bias + online softmax (log2 domain) ----
        float mx0 = -INFINITY, mx1 = -INFINITY;
        #pragma unroll
        for (int j = 0; j < 4; j++) {
            float2 bb = *(float2*)&sbias[kt * AKT + j * 8 + 2 * gt];
            sacc[j][0] = fmaf(sacc[j][0], LOG2E, bb.x);
            sacc[j][1] = fmaf(sacc[j][1], LOG2E, bb.y);
            sacc[j][2] = fmaf(sacc[j][2], LOG2E, bb.x);
            sacc[j][3] = fmaf(sacc[j][3], LOG2E, bb.y);
            mx0 = fmaxf(mx0, fmaxf(sacc[j][0], sacc[j][1]));
            mx1 = fmaxf(mx1, fmaxf(sacc[j][2], sacc[j][3]));
        }
        mx0 = fmaxf(mx0, __shfl_xor_sync(0xFFFFFFFF, mx0, 1));
        mx0 = fmaxf(mx0, __shfl_xor_sync(0xFFFFFFFF, mx0, 2));
        mx1 = fmaxf(mx1, __shfl_xor_sync(0xFFFFFFFF, mx1, 1));
        mx1 = fmaxf(mx1, __shfl_xor_sync(0xFFFFFFFF, mx1, 2));
        float mn0 = fmaxf(m0, mx0), mn1 = fmaxf(m1, mx1);
        float c0 = ex2(m0 - mn0), c1 = ex2(m1 - mn1);
        m0 = mn0; m1 = mn1;
        l0 *= c0;  l1 *= c1;
        #pragma unroll
        for (int j = 0; j < 8; j++) {
            oacc[j][0] *= c0; oacc[j][1] *= c0;
            oacc[j][2] *= c1; oacc[j][3] *= c1;
        }

        // ---- P = ex2(S - m), fp16 (hi only) ----
        uint32_t phiA[2][4];
        float ls0 = 0.0f, ls1 = 0.0f;
        #pragma unroll
        for (int j = 0; j < 4; j++) {
            float p0 = ex2(sacc[j][0] - mn0);
            float p1 = ex2(sacc[j][1] - mn0);
            float p2 = ex2(sacc[j][2] - mn1);
            float p3 = ex2(sacc[j][3] - mn1);
            ls0 += p0 + p1; ls1 += p2 + p3;
            int t = j >> 1, hf = (j & 1) * 2;
            phiA[t][hf + 0] = packh2(p0, p1);
            phiA[t][hf + 1] = packh2(p2, p3);
        }
        l0 += ls0; l1 += ls1;

        // ---- O += Phi . Vhi ----
        #pragma unroll
        for (int t = 0; t < 2; t++) {
            int rowb2 = t * 16 + rowb;
            uint32_t vhi[8][2];
            #pragma unroll
            for (int nc = 0; nc < 4; nc++) {
                uint32_t rr[4];
                ldmatrix_x4_trans(rr, Vst +
                    SW128((uint32_t)(rowb2 * 128 + nc * 32 + lc16)));
                vhi[nc * 2 + 0][0] = rr[0]; vhi[nc * 2 + 0][1] = rr[1];
                vhi[nc * 2 + 1][0] = rr[2]; vhi[nc * 2 + 1][1] = rr[3];
            }
            #pragma unroll
            for (int jn = 0; jn < 8; jn++)
                mma_fp16(oacc[jn], phiA[t], vhi[jn]);   // Phi * Vhi
        }
        __syncthreads();
    }

    l0 += __shfl_xor_sync(0xFFFFFFFF, l0, 1);
    l0 += __shfl_xor_sync(0xFFFFFFFF, l0, 2);
    l1 += __shfl_xor_sync(0xFFFFFFFF, l1, 1);
    l1 += __shfl_xor_sync(0xFFFFFFFF, l1, 2);
    float inv0 = 1.0f / l0, inv1 = 1.0f / l1;

    int r0 = qr0 + qw + gq;
    int r1 = r0 + 8;
    float* o0 = out + ((size_t)b * SEQL + r0) * DM + h_ * D;
    float* o1 = out + ((size_t)b * SEQL + r1) * DM + h_ * D;
    #pragma unroll
    for (int jn = 0; jn < 8; jn++) {
        int dc = jn * 8 + 2 * gt;
        *(float2*)(o0 + dc) = float2{oacc[jn][0] * inv0, oacc[jn][1] * inv0};
        *(float2*)(o1 + dc) = float2{oacc[jn][2] * inv1, oacc[jn][3] * inv1};
    }
}

// ---------------------------------------------------------------------------
extern "C" void kernel_launch(void* const* d_in, const int* in_sizes, int n_in,
                              void* d_out, int out_size)
{
    const float* X    = (const float*)d_in[0];
    const int*   mask = (const int*)  d_in[1];
    const float* Wq   = (const float*)d_in[2];
    const float* bq   = (const float*)d_in[3];
    const float* Wk   = (const float*)d_in[4];
    const float* bk   = (const float*)d_in[5];
    const float* Wv   = (const float*)d_in[6];
    const float* bv   = (const float*)d_in[7];

    __half* xh; cudaGetSymbolAddress((void**)&xh, g_Xh);
    __half* wh; cudaGetSymbolAddress((void**)&wh, g_Wh);

    // 1) fused split: X and W -> fp16 hi-only
    split_all_kernel<<<R + 3 * DM, 256>>>(X, Wq, Wk, Wv, xh, wh);

    // 2) QKV projection (fp16 1-term) -> Q fp16 hi|lo, K/V fp16 hi
    cudaFuncSetAttribute(qkv_mma_kernel,
                         cudaFuncAttributeMaxDynamicSharedMemorySize, PROJ_SMEM);
    dim3 g1(DM / BN, R / BM, 3);                           // (8, 32, 3)
    qkv_mma_kernel<<<g1, 256, PROJ_SMEM>>>(bq, bk, bv);

    // 3) attention (QK 2-term, PV 1-term)
    cudaFuncSetAttribute(attn_mma_kernel,
                         cudaFuncAttributeMaxDynamicSharedMemorySize, ATT_SMEM);
    dim3 g2(SEQL / 128, NBH);
    attn_mma_kernel<<<g2, 256, ATT_SMEM>>>(mask, (float*)d_out);
}